// round 1
// baseline (speedup 1.0000x reference)
#include <cuda_runtime.h>
#include <math.h>

#define TT 512
#define BB 64
#define DD 512
#define HH 512
#define GG 2048   // 4H

// ---------------- scratch (static device allocations only) ----------------
__device__ float g_xg[2][TT * BB][GG];     // precomputed x@Wih^T + bias, 512 MB
__device__ float g_h[2][2][HH][BB];        // [buf][dir][k][b]  (transposed h state)
__device__ float g_c[2][HH][BB];           // [dir][k][b]
__device__ unsigned g_bar_count[2];
__device__ volatile unsigned g_bar_gen[2];

// ---------------- per-direction grid barrier (64 CTAs each) ----------------
__device__ __forceinline__ void dir_barrier(int dir, unsigned target) {
    __syncthreads();
    if (threadIdx.x == 0) {
        __threadfence();
        if (atomicAdd(&g_bar_count[dir], 1u) == 63u) {
            g_bar_count[dir] = 0u;
            __threadfence();
            g_bar_gen[dir] = target;
        } else {
            while ((int)(g_bar_gen[dir] - target) < 0) { }
            __threadfence();
        }
    }
    __syncthreads();
}

// ---------------- kernel 1: Xg = x @ Wih^T + (bih + bhh) -------------------
// M = T*B = 32768 rows, N = 2048, K = 512. dir 1 reads x time-reversed.
__global__ void __launch_bounds__(256)
precompute_gates(const float* __restrict__ x,
                 const float* __restrict__ Wih_f,
                 const float* __restrict__ Wih_r,
                 const float* __restrict__ bih_f,
                 const float* __restrict__ bhh_f,
                 const float* __restrict__ bih_r,
                 const float* __restrict__ bhh_r)
{
    __shared__ float As[8][132];
    __shared__ float Bs[8][132];
    const int dir = blockIdx.z;
    const int n0  = blockIdx.x * 128;
    const int m0  = blockIdx.y * 128;
    const int tid = threadIdx.x;
    const int tx  = tid & 15;
    const int ty  = tid >> 4;
    const float* Wih = dir ? Wih_r : Wih_f;
    const float* bi  = dir ? bih_r : bih_f;
    const float* bh  = dir ? bhh_r : bhh_f;

    const int lrow = tid >> 1;
    const int lseg = tid & 1;
    const int mrow = m0 + lrow;
    const int asrc = dir ? ((TT - 1 - (mrow >> 6)) * BB + (mrow & 63)) : mrow;
    const float* Ap = x   + (size_t)asrc * DD + lseg * 4;
    const float* Bp = Wih + (size_t)(n0 + lrow) * DD + lseg * 4;

    float acc[8][8];
#pragma unroll
    for (int r = 0; r < 8; r++)
#pragma unroll
        for (int c = 0; c < 8; c++) acc[r][c] = 0.f;

    for (int k0 = 0; k0 < DD; k0 += 8) {
        float4 av = *(const float4*)(Ap + k0);
        float4 bv = *(const float4*)(Bp + k0);
        As[lseg * 4 + 0][lrow] = av.x;
        As[lseg * 4 + 1][lrow] = av.y;
        As[lseg * 4 + 2][lrow] = av.z;
        As[lseg * 4 + 3][lrow] = av.w;
        Bs[lseg * 4 + 0][lrow] = bv.x;
        Bs[lseg * 4 + 1][lrow] = bv.y;
        Bs[lseg * 4 + 2][lrow] = bv.z;
        Bs[lseg * 4 + 3][lrow] = bv.w;
        __syncthreads();
#pragma unroll
        for (int kk = 0; kk < 8; kk++) {
            float4 a0 = *(const float4*)&As[kk][ty * 4];
            float4 a1 = *(const float4*)&As[kk][64 + ty * 4];
            float4 b0 = *(const float4*)&Bs[kk][tx * 4];
            float4 b1 = *(const float4*)&Bs[kk][64 + tx * 4];
            float a[8] = {a0.x, a0.y, a0.z, a0.w, a1.x, a1.y, a1.z, a1.w};
            float b[8] = {b0.x, b0.y, b0.z, b0.w, b1.x, b1.y, b1.z, b1.w};
#pragma unroll
            for (int r = 0; r < 8; r++)
#pragma unroll
                for (int c = 0; c < 8; c++)
                    acc[r][c] += a[r] * b[c];
        }
        __syncthreads();
    }

#pragma unroll
    for (int r = 0; r < 8; r++) {
        int m = m0 + (r < 4 ? ty * 4 + r : 64 + ty * 4 + (r - 4));
        float* orow = &g_xg[dir][m][0];
#pragma unroll
        for (int ch = 0; ch < 2; ch++) {
            int n = n0 + (ch ? 64 + tx * 4 : tx * 4);
            float4 v;
            v.x = acc[r][ch * 4 + 0] + bi[n + 0] + bh[n + 0];
            v.y = acc[r][ch * 4 + 1] + bi[n + 1] + bh[n + 1];
            v.z = acc[r][ch * 4 + 2] + bi[n + 2] + bh[n + 2];
            v.w = acc[r][ch * 4 + 3] + bi[n + 3] + bh[n + 3];
            *(float4*)(orow + n) = v;
        }
    }
}

// ---------------- kernel 2: persistent recurrence --------------------------
// 128 CTAs: CTA = dir*64 + hblk. Each CTA owns h columns [hblk*8, hblk*8+8)
// for its direction: it computes the 32 gate columns {g*512 + hc} for all 64
// batches (M=64, N=32, K=512 GEMM vs resident-in-smem Whh slice), applies
// activations + mask, writes h (double-buffered), c, and the output slice.
__global__ void __launch_bounds__(256, 1)
lstm_rec_kernel(const float* __restrict__ mask,
                const float* __restrict__ Whh_f,
                const float* __restrict__ Whh_r,
                float* __restrict__ out)
{
    extern __shared__ float smem[];
    float* Ws = smem;                  // [512][32]  k-major Whh slice, 64 KB
    float* Hs = smem + 512 * 32;       // [32][64]   h chunk (k-major)
    float* Gs = Hs + 32 * 64;          // [64][33]   staged gate GEMM results

    const int tid = threadIdx.x;
    const int cta = blockIdx.x;
    const int dir = cta >> 6;
    const int hc0 = (cta & 63) * 8;
    const int tx  = tid & 15;
    const int ty  = tid >> 4;
    const float* Whh = dir ? Whh_r : Whh_f;

    // Load this CTA's 32 Whh rows (k-major) into shared, once.
    for (int q = tid; q < 32 * 128; q += 256) {
        int jl = q >> 7;                 // 0..31 local gate column
        int ks = (q & 127) << 2;         // k start
        int jg = ((jl >> 3) << 9) + hc0 + (jl & 7);
        float4 w = *(const float4*)(Whh + (size_t)jg * HH + ks);
        Ws[(ks + 0) * 32 + jl] = w.x;
        Ws[(ks + 1) * 32 + jl] = w.y;
        Ws[(ks + 2) * 32 + jl] = w.z;
        Ws[(ks + 3) * 32 + jl] = w.w;
    }

    // Zero own h/c slices (both h buffers).
    for (int q = tid; q < 512; q += 256) {
        int u = q >> 6, b = q & 63;
        g_h[0][dir][hc0 + u][b] = 0.f;
        g_h[1][dir][hc0 + u][b] = 0.f;
        g_c[dir][hc0 + u][b]    = 0.f;
    }
    const unsigned gen0 = g_bar_gen[dir];
    dir_barrier(dir, gen0 + 1);

    for (int t = 0; t < TT; t++) {
        const int buf = t & 1;
        const float* hsrc = &g_h[buf][dir][0][0];

        float acc[4][2];
#pragma unroll
        for (int r = 0; r < 4; r++) { acc[r][0] = 0.f; acc[r][1] = 0.f; }

        for (int kc = 0; kc < 16; kc++) {
#pragma unroll
            for (int i = 0; i < 2; i++) {
                int q  = i * 256 + tid;
                int kr = q >> 4;
                int b4 = (q & 15) << 2;
                // h written by other CTAs -> bypass (incoherent) L1
                float4 hv = __ldcg((const float4*)(hsrc + (kc * 32 + kr) * 64 + b4));
                *(float4*)&Hs[kr * 64 + b4] = hv;
            }
            __syncthreads();
#pragma unroll
            for (int kr = 0; kr < 32; kr++) {
                float4 h4 = *(const float4*)&Hs[kr * 64 + ty * 4];
                float2 w2 = *(const float2*)&Ws[(kc * 32 + kr) * 32 + tx * 2];
                acc[0][0] += h4.x * w2.x; acc[0][1] += h4.x * w2.y;
                acc[1][0] += h4.y * w2.x; acc[1][1] += h4.y * w2.y;
                acc[2][0] += h4.z * w2.x; acc[2][1] += h4.z * w2.y;
                acc[3][0] += h4.w * w2.x; acc[3][1] += h4.w * w2.y;
            }
            __syncthreads();
        }

        // Stage gate GEMM results: Gs[b][jl], jl = g*8 + u
#pragma unroll
        for (int r = 0; r < 4; r++) {
            Gs[(ty * 4 + r) * 33 + tx * 2 + 0] = acc[r][0];
            Gs[(ty * 4 + r) * 33 + tx * 2 + 1] = acc[r][1];
        }
        __syncthreads();

        const int tt = dir ? (TT - 1 - t) : t;   // time index & output row
#pragma unroll
        for (int pp = 0; pp < 2; pp++) {
            int p = pp * 256 + tid;
            int b = p >> 3, u = p & 7;
            const float* xg = &g_xg[dir][(size_t)t * BB + b][0];

            float iv = xg[hc0 + u]        + Gs[b * 33 + u];
            float fv = xg[512 + hc0 + u]  + Gs[b * 33 + 8 + u];
            float gv = xg[1024 + hc0 + u] + Gs[b * 33 + 16 + u];
            float ov = xg[1536 + hc0 + u] + Gs[b * 33 + 24 + u];
            iv = 1.f / (1.f + __expf(-iv));
            fv = 1.f / (1.f + __expf(-fv));
            gv = tanhf(gv);
            ov = 1.f / (1.f + __expf(-ov));

            float cold = g_c[dir][hc0 + u][b];
            float hold = g_h[buf][dir][hc0 + u][b];   // own slice (L1-safe)
            float cn = fv * cold + iv * gv;
            float hn = ov * tanhf(cn);
            float m  = mask[tt * BB + b];
            cn = m * cn + (1.f - m) * cold;
            hn = m * hn + (1.f - m) * hold;

            g_c[dir][hc0 + u][b] = cn;
            __stcg(&g_h[buf ^ 1][dir][hc0 + u][b], hn);
            out[(size_t)tt * (BB * 2 * HH) + (size_t)b * (2 * HH) + (dir << 9) + hc0 + u] = hn;
        }
        dir_barrier(dir, gen0 + 2 + t);
    }
}

// ---------------- launch ----------------------------------------------------
extern "C" void kernel_launch(void* const* d_in, const int* in_sizes, int n_in,
                              void* d_out, int out_size) {
    const float* x     = (const float*)d_in[0];
    const float* mask  = (const float*)d_in[1];
    const float* Wih_f = (const float*)d_in[2];
    const float* Whh_f = (const float*)d_in[3];
    const float* bih_f = (const float*)d_in[4];
    const float* bhh_f = (const float*)d_in[5];
    const float* Wih_r = (const float*)d_in[6];
    const float* Whh_r = (const float*)d_in[7];
    const float* bih_r = (const float*)d_in[8];
    const float* bhh_r = (const float*)d_in[9];
    float* out = (float*)d_out;

    dim3 grid(GG / 128, (TT * BB) / 128, 2);
    precompute_gates<<<grid, 256>>>(x, Wih_f, Wih_r, bih_f, bhh_f, bih_r, bhh_r);

    const int smem_bytes = (512 * 32 + 32 * 64 + 64 * 33) * 4;  // 82176
    cudaFuncSetAttribute(lstm_rec_kernel,
                         cudaFuncAttributeMaxDynamicSharedMemorySize, smem_bytes);
    lstm_rec_kernel<<<128, 256, smem_bytes>>>(mask, Whh_f, Whh_r, out);
}

// round 2
// speedup vs baseline: 1.0091x; 1.0091x over previous
#include <cuda_runtime.h>
#include <math.h>
#include <stdint.h>

#define TT 512
#define BB 64
#define DD 512
#define HH 512
#define GG 2048   // 4H

// ---------------- scratch (static device allocations only) ----------------
__device__ float g_xg[2][TT * BB][GG];     // precomputed x@Wih^T + bias, 512 MB
__device__ float g_h[2][2][HH][BB];        // [buf][dir][k][b]  (transposed h state)
__device__ unsigned g_bar_count[2];
__device__ volatile unsigned g_bar_gen[2];
__device__ volatile unsigned g_flag[2][64];

// ---------------- init-only per-direction grid barrier ---------------------
__device__ __forceinline__ void dir_barrier(int dir, unsigned target) {
    __syncthreads();
    if (threadIdx.x == 0) {
        __threadfence();
        if (atomicAdd(&g_bar_count[dir], 1u) == 63u) {
            g_bar_count[dir] = 0u;
            __threadfence();
            g_bar_gen[dir] = target;
        } else {
            while ((int)(g_bar_gen[dir] - target) < 0) { }
            __threadfence();
        }
    }
    __syncthreads();
}

__device__ __forceinline__ void cp_async16(uint32_t dst, const void* src) {
    asm volatile("cp.async.cg.shared.global [%0], [%1], 16;" :: "r"(dst), "l"(src));
}
__device__ __forceinline__ void cp_commit() { asm volatile("cp.async.commit_group;"); }
__device__ __forceinline__ void cp_wait0()  { asm volatile("cp.async.wait_group 0;"); }

// ---------------- kernel 1: Xg = x @ Wih^T + (bih + bhh) -------------------
__global__ void __launch_bounds__(256)
precompute_gates(const float* __restrict__ x,
                 const float* __restrict__ Wih_f,
                 const float* __restrict__ Wih_r,
                 const float* __restrict__ bih_f,
                 const float* __restrict__ bhh_f,
                 const float* __restrict__ bih_r,
                 const float* __restrict__ bhh_r)
{
    __shared__ float As[8][132];
    __shared__ float Bs[8][132];
    const int dir = blockIdx.z;
    const int n0  = blockIdx.x * 128;
    const int m0  = blockIdx.y * 128;
    const int tid = threadIdx.x;
    const int tx  = tid & 15;
    const int ty  = tid >> 4;
    const float* Wih = dir ? Wih_r : Wih_f;
    const float* bi  = dir ? bih_r : bih_f;
    const float* bh  = dir ? bhh_r : bhh_f;

    const int lrow = tid >> 1;
    const int lseg = tid & 1;
    const int mrow = m0 + lrow;
    const int asrc = dir ? ((TT - 1 - (mrow >> 6)) * BB + (mrow & 63)) : mrow;
    const float* Ap = x   + (size_t)asrc * DD + lseg * 4;
    const float* Bp = Wih + (size_t)(n0 + lrow) * DD + lseg * 4;

    float acc[8][8];
#pragma unroll
    for (int r = 0; r < 8; r++)
#pragma unroll
        for (int c = 0; c < 8; c++) acc[r][c] = 0.f;

    for (int k0 = 0; k0 < DD; k0 += 8) {
        float4 av = *(const float4*)(Ap + k0);
        float4 bv = *(const float4*)(Bp + k0);
        As[lseg * 4 + 0][lrow] = av.x;
        As[lseg * 4 + 1][lrow] = av.y;
        As[lseg * 4 + 2][lrow] = av.z;
        As[lseg * 4 + 3][lrow] = av.w;
        Bs[lseg * 4 + 0][lrow] = bv.x;
        Bs[lseg * 4 + 1][lrow] = bv.y;
        Bs[lseg * 4 + 2][lrow] = bv.z;
        Bs[lseg * 4 + 3][lrow] = bv.w;
        __syncthreads();
#pragma unroll
        for (int kk = 0; kk < 8; kk++) {
            float4 a0 = *(const float4*)&As[kk][ty * 4];
            float4 a1 = *(const float4*)&As[kk][64 + ty * 4];
            float4 b0 = *(const float4*)&Bs[kk][tx * 4];
            float4 b1 = *(const float4*)&Bs[kk][64 + tx * 4];
            float a[8] = {a0.x, a0.y, a0.z, a0.w, a1.x, a1.y, a1.z, a1.w};
            float b[8] = {b0.x, b0.y, b0.z, b0.w, b1.x, b1.y, b1.z, b1.w};
#pragma unroll
            for (int r = 0; r < 8; r++)
#pragma unroll
                for (int c = 0; c < 8; c++)
                    acc[r][c] += a[r] * b[c];
        }
        __syncthreads();
    }

#pragma unroll
    for (int r = 0; r < 8; r++) {
        int m = m0 + (r < 4 ? ty * 4 + r : 64 + ty * 4 + (r - 4));
        float* orow = &g_xg[dir][m][0];
#pragma unroll
        for (int ch = 0; ch < 2; ch++) {
            int n = n0 + (ch ? 64 + tx * 4 : tx * 4);
            float4 v;
            v.x = acc[r][ch * 4 + 0] + bi[n + 0] + bh[n + 0];
            v.y = acc[r][ch * 4 + 1] + bi[n + 1] + bh[n + 1];
            v.z = acc[r][ch * 4 + 2] + bi[n + 2] + bh[n + 2];
            v.w = acc[r][ch * 4 + 3] + bi[n + 3] + bh[n + 3];
            *(float4*)(orow + n) = v;
        }
    }
}

// ---------------- kernel 2: persistent recurrence --------------------------
// 128 CTAs (64/dir), 128 threads. CTA owns h units [hc0, hc0+8) => 32 gate
// cols x 64 batches, K=512 GEMM vs smem-resident Whh slice. 4x4 acc/thread.
// Double-buffered Hs chunks via cp.async.cg; flag-array step barrier;
// c and h_prev live in registers.

#define WS_OFF   0            // Ws[512][32]
#define HS_OFF   16384        // Hs[2][64][68]
#define HS_BUF   (64 * 68)
#define GS_OFF   (16384 + 2 * HS_BUF)   // Gs[64][36]
#define SMEM_FLOATS (GS_OFF + 64 * 36)

__global__ void __launch_bounds__(128, 1)
lstm_rec_kernel(const float* __restrict__ mask,
                const float* __restrict__ Whh_f,
                const float* __restrict__ Whh_r,
                float* __restrict__ out)
{
    extern __shared__ float smem[];
    float* Ws = smem + WS_OFF;
    float* Hs = smem + HS_OFF;
    float* Gs = smem + GS_OFF;
    const uint32_t hs_base = (uint32_t)__cvta_generic_to_shared(Hs);

    const int tid = threadIdx.x;
    const int cta = blockIdx.x;
    const int dir = cta >> 6;
    const int hc0 = (cta & 63) * 8;
    const int tx  = tid & 7;      // GEMM: 4 cols at tx*4
    const int ty  = tid >> 3;     // GEMM: 4 batches at ty*4
    const int pu  = tid >> 4;     // pointwise: h unit
    const int pb  = tid & 15;     // pointwise: batch base
    const float* Whh = dir ? Whh_r : Whh_f;

    // Load this CTA's 32 Whh rows (k-major) into shared, once.
    for (int q = tid; q < 32 * 128; q += 128) {
        int jl = q >> 7;
        int ks = (q & 127) << 2;
        int jg = ((jl >> 3) << 9) + hc0 + (jl & 7);
        float4 w = *(const float4*)(Whh + (size_t)jg * HH + ks);
        Ws[(ks + 0) * 32 + jl] = w.x;
        Ws[(ks + 1) * 32 + jl] = w.y;
        Ws[(ks + 2) * 32 + jl] = w.z;
        Ws[(ks + 3) * 32 + jl] = w.w;
    }

    // Zero own slice of h buffer 0; reset own step flag.
    for (int q = tid; q < 512; q += 128) {
        int u = q >> 6, b = q & 63;
        g_h[0][dir][hc0 + u][b] = 0.f;
    }
    if (tid == 0) g_flag[dir][cta & 63] = 0u;
    const unsigned gen0 = g_bar_gen[dir];
    dir_barrier(dir, gen0 + 1);

    // Register-resident cell state (fixed (u,b) ownership per thread).
    float c_reg[4]  = {0.f, 0.f, 0.f, 0.f};
    float h_prev[4] = {0.f, 0.f, 0.f, 0.f};

    for (int t = 0; t < TT; t++) {
        const int buf = t & 1;
        const float* hsrc = &g_h[buf][dir][0][0];
        const int tt = dir ? (TT - 1 - t) : t;

        // --- prefetch xg gates for the pointwise phase (DRAM, hidden) ---
        float xgi[4], xgf[4], xgg[4], xgo[4];
#pragma unroll
        for (int i = 0; i < 4; i++) {
            const float* xr = &g_xg[dir][(size_t)t * BB + (i * 16 + pb)][0];
            xgi[i] = __ldg(xr + hc0 + pu);
            xgf[i] = __ldg(xr + 512 + hc0 + pu);
            xgg[i] = __ldg(xr + 1024 + hc0 + pu);
            xgo[i] = __ldg(xr + 1536 + hc0 + pu);
        }
        float mv[4];
#pragma unroll
        for (int i = 0; i < 4; i++) mv[i] = __ldg(&mask[tt * BB + i * 16 + pb]);

        // --- wait for all h[t] slices ---
        if (tid < 64) {
            while (g_flag[dir][tid] < (unsigned)t) { }
        }
        __syncthreads();

        // --- prefetch chunk 0 of h into Hs buf 0 ---
#pragma unroll
        for (int j = 0; j < 8; j++) {
            int idx = j * 128 + tid;
            int kr = idx >> 4, b4 = (idx & 15) << 2;
            cp_async16(hs_base + (uint32_t)((kr * 68 + b4) << 2),
                       hsrc + kr * 64 + b4);
        }
        cp_commit();

        float acc[4][4];
#pragma unroll
        for (int r = 0; r < 4; r++)
#pragma unroll
            for (int c = 0; c < 4; c++) acc[r][c] = 0.f;

        for (int kc = 0; kc < 8; kc++) {
            cp_wait0();
            __syncthreads();
            if (kc < 7) {
                const float* src = hsrc + (kc + 1) * 64 * 64;
                uint32_t dst = hs_base + (uint32_t)((((kc + 1) & 1) * HS_BUF) << 2);
#pragma unroll
                for (int j = 0; j < 8; j++) {
                    int idx = j * 128 + tid;
                    int kr = idx >> 4, b4 = (idx & 15) << 2;
                    cp_async16(dst + (uint32_t)((kr * 68 + b4) << 2),
                               src + kr * 64 + b4);
                }
                cp_commit();
            }
            const float* Hb = Hs + (kc & 1) * HS_BUF;
            const float* Wb = Ws + kc * 64 * 32;
#pragma unroll 8
            for (int kr = 0; kr < 64; kr++) {
                float4 h4 = *(const float4*)&Hb[kr * 68 + ty * 4];
                float4 w4 = *(const float4*)&Wb[kr * 32 + tx * 4];
                float hr[4] = {h4.x, h4.y, h4.z, h4.w};
                float wc[4] = {w4.x, w4.y, w4.z, w4.w};
#pragma unroll
                for (int r = 0; r < 4; r++)
#pragma unroll
                    for (int c = 0; c < 4; c++)
                        acc[r][c] += hr[r] * wc[c];
            }
        }

        // --- stage gate GEMM results: Gs[b][jl] ---
#pragma unroll
        for (int r = 0; r < 4; r++)
            *(float4*)&Gs[(ty * 4 + r) * 36 + tx * 4] =
                make_float4(acc[r][0], acc[r][1], acc[r][2], acc[r][3]);
        __syncthreads();

        // --- pointwise: thread owns (u=pu, b in {pb, pb+16, pb+32, pb+48}) ---
#pragma unroll
        for (int i = 0; i < 4; i++) {
            int b = i * 16 + pb;
            float iv = xgi[i] + Gs[b * 36 + pu];
            float fv = xgf[i] + Gs[b * 36 + 8 + pu];
            float gv = xgg[i] + Gs[b * 36 + 16 + pu];
            float ov = xgo[i] + Gs[b * 36 + 24 + pu];
            iv = 1.f / (1.f + __expf(-iv));
            fv = 1.f / (1.f + __expf(-fv));
            gv = tanhf(gv);
            ov = 1.f / (1.f + __expf(-ov));

            float cn = fv * c_reg[i] + iv * gv;
            float hn = ov * tanhf(cn);
            float m  = mv[i];
            cn = m * cn + (1.f - m) * c_reg[i];
            hn = m * hn + (1.f - m) * h_prev[i];
            c_reg[i]  = cn;
            h_prev[i] = hn;

            __stcg(&g_h[buf ^ 1][dir][hc0 + pu][b], hn);
            out[(size_t)tt * (BB * 2 * HH) + (size_t)b * (2 * HH)
                + (dir << 9) + hc0 + pu] = hn;
        }
        __syncthreads();
        if (tid == 0) {
            __threadfence();
            g_flag[dir][cta & 63] = (unsigned)(t + 1);
        }
    }
}

// ---------------- launch ----------------------------------------------------
extern "C" void kernel_launch(void* const* d_in, const int* in_sizes, int n_in,
                              void* d_out, int out_size) {
    const float* x     = (const float*)d_in[0];
    const float* mask  = (const float*)d_in[1];
    const float* Wih_f = (const float*)d_in[2];
    const float* Whh_f = (const float*)d_in[3];
    const float* bih_f = (const float*)d_in[4];
    const float* bhh_f = (const float*)d_in[5];
    const float* Wih_r = (const float*)d_in[6];
    const float* Whh_r = (const float*)d_in[7];
    const float* bih_r = (const float*)d_in[8];
    const float* bhh_r = (const float*)d_in[9];
    float* out = (float*)d_out;

    dim3 grid(GG / 128, (TT * BB) / 128, 2);
    precompute_gates<<<grid, 256>>>(x, Wih_f, Wih_r, bih_f, bhh_f, bih_r, bhh_r);

    const int smem_bytes = SMEM_FLOATS * 4;   // ~109.5 KB
    cudaFuncSetAttribute(lstm_rec_kernel,
                         cudaFuncAttributeMaxDynamicSharedMemorySize, smem_bytes);
    lstm_rec_kernel<<<128, 128, smem_bytes>>>(mask, Whh_f, Whh_r, out);
}

// round 11
// speedup vs baseline: 1.2060x; 1.1951x over previous
#include <cuda_runtime.h>
#include <cuda_bf16.h>
#include <math.h>
#include <stdint.h>

#define TT 512
#define BB 64
#define DD 512
#define HH 512
#define GG 2048   // 4H

// ---------------- scratch (static device allocations only) ----------------
__device__ float g_xg[2][TT * BB][GG];          // precomputed x@Wih^T + bias
__device__ float g_h[2][2][HH][BB];             // [buf][dir][k][b]
__device__ unsigned g_bar_count[2];
__device__ volatile unsigned g_bar_gen[2];
__device__ volatile unsigned g_flag[2][64];
__device__ __nv_bfloat16 g_xh[TT * BB * DD];    // x split hi
__device__ __nv_bfloat16 g_xl[TT * BB * DD];    // x split lo
__device__ __nv_bfloat16 g_wh[2][GG * DD];      // Wih split hi (per dir)
__device__ __nv_bfloat16 g_wl[2][GG * DD];      // Wih split lo

// ---------------- PTX helpers (baseline ISA only — no tcgen05!) ------------
__device__ __forceinline__ uint32_t smem_to_u32(const void* p) {
    uint32_t a;
    asm("{ .reg .u64 t; cvta.to.shared.u64 t, %1; cvt.u32.u64 %0, t; }"
        : "=r"(a) : "l"(p));
    return a;
}
__device__ __forceinline__ void cp_async16(uint32_t dst, const void* src) {
    asm volatile("cp.async.cg.shared.global [%0], [%1], 16;" :: "r"(dst), "l"(src));
}
__device__ __forceinline__ void cp_commit() { asm volatile("cp.async.commit_group;"); }
__device__ __forceinline__ void cp_wait0()  { asm volatile("cp.async.wait_group 0;"); }

__device__ __forceinline__ void ldsm_x4(uint32_t* r, uint32_t a) {
    asm volatile("ldmatrix.sync.aligned.m8n8.x4.shared.b16 {%0,%1,%2,%3}, [%4];"
                 : "=r"(r[0]), "=r"(r[1]), "=r"(r[2]), "=r"(r[3]) : "r"(a));
}
__device__ __forceinline__ void ldsm_x2(uint32_t* r, uint32_t a) {
    asm volatile("ldmatrix.sync.aligned.m8n8.x2.shared.b16 {%0,%1}, [%2];"
                 : "=r"(r[0]), "=r"(r[1]) : "r"(a));
}
__device__ __forceinline__ void mma16816(float* c, const uint32_t* a, const uint32_t* b) {
    asm volatile("mma.sync.aligned.m16n8k16.row.col.f32.bf16.bf16.f32 "
                 "{%0,%1,%2,%3}, {%4,%5,%6,%7}, {%8,%9}, {%0,%1,%2,%3};"
                 : "+f"(c[0]), "+f"(c[1]), "+f"(c[2]), "+f"(c[3])
                 : "r"(a[0]), "r"(a[1]), "r"(a[2]), "r"(a[3]), "r"(b[0]), "r"(b[1]));
}

// ---------------- grid barrier (rec init) -----------------------------------
__device__ __forceinline__ void dir_barrier(int dir, unsigned target) {
    __syncthreads();
    if (threadIdx.x == 0) {
        __threadfence();
        if (atomicAdd(&g_bar_count[dir], 1u) == 63u) {
            g_bar_count[dir] = 0u;
            __threadfence();
            g_bar_gen[dir] = target;
        } else {
            while ((int)(g_bar_gen[dir] - target) < 0) { }
            __threadfence();
        }
    }
    __syncthreads();
}

// ---------------- kernel 0: fp32 -> bf16 hi/lo split -------------------------
__global__ void __launch_bounds__(256)
split_bf16(const float* __restrict__ src, __nv_bfloat16* __restrict__ hi,
           __nv_bfloat16* __restrict__ lo) {
    int i = (blockIdx.x * 256 + threadIdx.x) * 4;
    float4 v = *(const float4*)(src + i);
    __nv_bfloat16 h[4], l[4];
    float f[4] = {v.x, v.y, v.z, v.w};
#pragma unroll
    for (int k = 0; k < 4; k++) {
        h[k] = __float2bfloat16(f[k]);
        l[k] = __float2bfloat16(f[k] - __bfloat162float(h[k]));
    }
    *(uint2*)(hi + i) = *(uint2*)h;
    *(uint2*)(lo + i) = *(uint2*)l;
}

// ---------------- kernel 1: mma.sync bf16-split precompute GEMM --------------
// C[128m x 128n]/CTA = Xg tile. 256 thr = 8 warps, warp = 64x32. K chunks of
// 32 (bf16), double-buffered cp.async. 3 split chains into fp32 accumulators.
// smem rows padded to 80B so ldmatrix's 8-row pattern is bank-conflict-free.
#define KC       32
#define ROW_B    80                    // padded row bytes (32 bf16 -> 64B + 16 pad)
#define TILE_PB  (128 * ROW_B)         // 10240 B per tile
#define STAGE_PB (4 * TILE_PB)         // Ah, Al, Bh, Bl
#define PRE_SMEM (512 + 2 * STAGE_PB)  // bias + 2 stages = 82432 B

__global__ void __launch_bounds__(256)
precompute_mma(const float* __restrict__ bih_f, const float* __restrict__ bhh_f,
               const float* __restrict__ bih_r, const float* __restrict__ bhh_r)
{
    extern __shared__ char smem[];
    float* bias_s = (float*)smem;
    const uint32_t tilesBase = smem_to_u32(smem) + 512;

    const int tid  = threadIdx.x;
    const int wid  = tid >> 5;
    const int lane = tid & 31;
    const int dir  = blockIdx.z;
    const int n0   = blockIdx.x * 128;
    const int m0   = blockIdx.y * 128;
    const int m_off = (wid >> 2) * 64;   // 0 or 64
    const int n_off = (wid & 3) * 32;    // 0,32,64,96

    const __nv_bfloat16* wh = g_wh[dir];
    const __nv_bfloat16* wl = g_wl[dir];
    const float* bi = dir ? bih_r : bih_f;
    const float* bh = dir ? bhh_r : bhh_f;
    if (tid < 128) bias_s[tid] = __ldg(bi + n0 + tid) + __ldg(bh + n0 + tid);

    // per-chunk stage load: 4 tiles x 128 rows x 4 (16B segs) = 2048 units
    auto load_chunk = [&](int c, int bf) {
        const uint32_t sbase = tilesBase + bf * STAGE_PB;
        const int k0 = c * KC;
#pragma unroll
        for (int j = 0; j < 8; j++) {
            int idx  = j * 256 + tid;
            int tile = idx >> 9;
            int u    = idx & 511;
            int row  = u >> 2, seg = u & 3;
            uint32_t dst = sbase + tile * TILE_PB + row * ROW_B + seg * 16;
            const __nv_bfloat16* src;
            if (tile < 2) {
                int m = m0 + row;
                int asrc = dir ? ((TT - 1 - (m >> 6)) * BB + (m & 63)) : m;
                src = (tile == 0 ? g_xh : g_xl) + (size_t)asrc * DD + k0 + seg * 8;
            } else {
                src = (tile == 2 ? wh : wl) + (size_t)(n0 + row) * DD + k0 + seg * 8;
            }
            cp_async16(dst, src);
        }
        cp_commit();
    };

    // per-lane ldmatrix base offsets (within a tile)
    const uint32_t aOff = (uint32_t)((m_off + (lane & 15)) * ROW_B + (lane >> 4) * 16);
    const uint32_t bOff = (uint32_t)((n_off + (lane & 7)) * ROW_B + ((lane >> 3) & 1) * 16);

    float acc[4][4][4];
#pragma unroll
    for (int mt = 0; mt < 4; mt++)
#pragma unroll
        for (int nt = 0; nt < 4; nt++)
#pragma unroll
            for (int q = 0; q < 4; q++) acc[mt][nt][q] = 0.f;

    load_chunk(0, 0);

    for (int c = 0; c < 16; c++) {
        cp_wait0();
        __syncthreads();
        if (c < 15) load_chunk(c + 1, (c + 1) & 1);
        const uint32_t stage = tilesBase + (c & 1) * STAGE_PB;

#pragma unroll
        for (int kk = 0; kk < 2; kk++) {
            uint32_t bhf[4][2], blf[4][2];
#pragma unroll
            for (int nt = 0; nt < 4; nt++) {
                ldsm_x2(bhf[nt], stage + 2 * TILE_PB + bOff + nt * 8 * ROW_B + kk * 32);
                ldsm_x2(blf[nt], stage + 3 * TILE_PB + bOff + nt * 8 * ROW_B + kk * 32);
            }
#pragma unroll
            for (int mt = 0; mt < 4; mt++) {
                uint32_t ahf[4], alf[4];
                ldsm_x4(ahf, stage + 0 * TILE_PB + aOff + mt * 16 * ROW_B + kk * 32);
                ldsm_x4(alf, stage + 1 * TILE_PB + aOff + mt * 16 * ROW_B + kk * 32);
#pragma unroll
                for (int nt = 0; nt < 4; nt++) {
                    mma16816(acc[mt][nt], ahf, bhf[nt]);
                    mma16816(acc[mt][nt], ahf, blf[nt]);
                    mma16816(acc[mt][nt], alf, bhf[nt]);
                }
            }
        }
    }

    // epilogue: C fragment -> g_xg with bias
    const int gid = lane >> 2, qid = lane & 3;
#pragma unroll
    for (int mt = 0; mt < 4; mt++) {
#pragma unroll
        for (int nt = 0; nt < 4; nt++) {
            int nl = n_off + nt * 8 + qid * 2;
            int ml0 = m_off + mt * 16 + gid;
            float2 v0 = make_float2(acc[mt][nt][0] + bias_s[nl],
                                    acc[mt][nt][1] + bias_s[nl + 1]);
            float2 v1 = make_float2(acc[mt][nt][2] + bias_s[nl],
                                    acc[mt][nt][3] + bias_s[nl + 1]);
            *(float2*)&g_xg[dir][m0 + ml0][n0 + nl]     = v0;
            *(float2*)&g_xg[dir][m0 + ml0 + 8][n0 + nl] = v1;
        }
    }
}

// ---------------- kernel 2: persistent recurrence (proven, round 2) ----------
#define WS_OFF   0
#define HS_OFF   16384
#define HS_BUF   (64 * 68)
#define GS_OFF   (16384 + 2 * HS_BUF)
#define SMEM_FLOATS (GS_OFF + 64 * 36)

__global__ void __launch_bounds__(128, 1)
lstm_rec_kernel(const float* __restrict__ mask,
                const float* __restrict__ Whh_f,
                const float* __restrict__ Whh_r,
                float* __restrict__ out)
{
    extern __shared__ float smemf[];
    float* Ws = smemf + WS_OFF;
    float* Hs = smemf + HS_OFF;
    float* Gs = smemf + GS_OFF;
    const uint32_t hs_base = (uint32_t)__cvta_generic_to_shared(Hs);

    const int tid = threadIdx.x;
    const int cta = blockIdx.x;
    const int dir = cta >> 6;
    const int hc0 = (cta & 63) * 8;
    const int tx  = tid & 7;
    const int ty  = tid >> 3;
    const int pu  = tid >> 4;
    const int pb  = tid & 15;
    const float* Whh = dir ? Whh_r : Whh_f;

    for (int q = tid; q < 32 * 128; q += 128) {
        int jl = q >> 7;
        int ks = (q & 127) << 2;
        int jg = ((jl >> 3) << 9) + hc0 + (jl & 7);
        float4 w = *(const float4*)(Whh + (size_t)jg * HH + ks);
        Ws[(ks + 0) * 32 + jl] = w.x;
        Ws[(ks + 1) * 32 + jl] = w.y;
        Ws[(ks + 2) * 32 + jl] = w.z;
        Ws[(ks + 3) * 32 + jl] = w.w;
    }
    for (int q = tid; q < 512; q += 128) {
        int u = q >> 6, b = q & 63;
        g_h[0][dir][hc0 + u][b] = 0.f;
    }
    if (tid == 0) g_flag[dir][cta & 63] = 0u;
    const unsigned gen0 = g_bar_gen[dir];
    dir_barrier(dir, gen0 + 1);

    float c_reg[4]  = {0.f, 0.f, 0.f, 0.f};
    float h_prev[4] = {0.f, 0.f, 0.f, 0.f};

    for (int t = 0; t < TT; t++) {
        const int buf = t & 1;
        const float* hsrc = &g_h[buf][dir][0][0];
        const int tt = dir ? (TT - 1 - t) : t;

        float xgi[4], xgf[4], xgg[4], xgo[4];
#pragma unroll
        for (int i = 0; i < 4; i++) {
            const float* xr = &g_xg[dir][(size_t)t * BB + (i * 16 + pb)][0];
            xgi[i] = __ldg(xr + hc0 + pu);
            xgf[i] = __ldg(xr + 512 + hc0 + pu);
            xgg[i] = __ldg(xr + 1024 + hc0 + pu);
            xgo[i] = __ldg(xr + 1536 + hc0 + pu);
        }
        float mv[4];
#pragma unroll
        for (int i = 0; i < 4; i++) mv[i] = __ldg(&mask[tt * BB + i * 16 + pb]);

        if (tid < 64) {
            while (g_flag[dir][tid] < (unsigned)t) { }
        }
        __syncthreads();

#pragma unroll
        for (int j = 0; j < 8; j++) {
            int idx = j * 128 + tid;
            int kr = idx >> 4, b4 = (idx & 15) << 2;
            cp_async16(hs_base + (uint32_t)((kr * 68 + b4) << 2), hsrc + kr * 64 + b4);
        }
        cp_commit();

        float acc[4][4];
#pragma unroll
        for (int r = 0; r < 4; r++)
#pragma unroll
            for (int c = 0; c < 4; c++) acc[r][c] = 0.f;

        for (int kc = 0; kc < 8; kc++) {
            cp_wait0();
            __syncthreads();
            if (kc < 7) {
                const float* src = hsrc + (kc + 1) * 64 * 64;
                uint32_t dst = hs_base + (uint32_t)((((kc + 1) & 1) * HS_BUF) << 2);
#pragma unroll
                for (int j = 0; j < 8; j++) {
                    int idx = j * 128 + tid;
                    int kr = idx >> 4, b4 = (idx & 15) << 2;
                    cp_async16(dst + (uint32_t)((kr * 68 + b4) << 2), src + kr * 64 + b4);
                }
                cp_commit();
            }
            const float* Hb = Hs + (kc & 1) * HS_BUF;
            const float* Wb = Ws + kc * 64 * 32;
#pragma unroll 8
            for (int kr = 0; kr < 64; kr++) {
                float4 h4 = *(const float4*)&Hb[kr * 68 + ty * 4];
                float4 w4 = *(const float4*)&Wb[kr * 32 + tx * 4];
                float hr[4] = {h4.x, h4.y, h4.z, h4.w};
                float wc[4] = {w4.x, w4.y, w4.z, w4.w};
#pragma unroll
                for (int r = 0; r < 4; r++)
#pragma unroll
                    for (int c = 0; c < 4; c++)
                        acc[r][c] += hr[r] * wc[c];
            }
        }

#pragma unroll
        for (int r = 0; r < 4; r++)
            *(float4*)&Gs[(ty * 4 + r) * 36 + tx * 4] =
                make_float4(acc[r][0], acc[r][1], acc[r][2], acc[r][3]);
        __syncthreads();

#pragma unroll
        for (int i = 0; i < 4; i++) {
            int b = i * 16 + pb;
            float iv = xgi[i] + Gs[b * 36 + pu];
            float fv = xgf[i] + Gs[b * 36 + 8 + pu];
            float gv = xgg[i] + Gs[b * 36 + 16 + pu];
            float ov = xgo[i] + Gs[b * 36 + 24 + pu];
            iv = 1.f / (1.f + __expf(-iv));
            fv = 1.f / (1.f + __expf(-fv));
            gv = tanhf(gv);
            ov = 1.f / (1.f + __expf(-ov));

            float cn = fv * c_reg[i] + iv * gv;
            float hn = ov * tanhf(cn);
            float m  = mv[i];
            cn = m * cn + (1.f - m) * c_reg[i];
            hn = m * hn + (1.f - m) * h_prev[i];
            c_reg[i]  = cn;
            h_prev[i] = hn;

            __stcg(&g_h[buf ^ 1][dir][hc0 + pu][b], hn);
            out[(size_t)tt * (BB * 2 * HH) + (size_t)b * (2 * HH)
                + (dir << 9) + hc0 + pu] = hn;
        }
        __syncthreads();
        if (tid == 0) {
            __threadfence();
            g_flag[dir][cta & 63] = (unsigned)(t + 1);
        }
    }
}

// ---------------- launch -----------------------------------------------------
extern "C" void kernel_launch(void* const* d_in, const int* in_sizes, int n_in,
                              void* d_out, int out_size) {
    const float* x     = (const float*)d_in[0];
    const float* mask  = (const float*)d_in[1];
    const float* Wih_f = (const float*)d_in[2];
    const float* Whh_f = (const float*)d_in[3];
    const float* bih_f = (const float*)d_in[4];
    const float* bhh_f = (const float*)d_in[5];
    const float* Wih_r = (const float*)d_in[6];
    const float* Whh_r = (const float*)d_in[7];
    const float* bih_r = (const float*)d_in[8];
    const float* bhh_r = (const float*)d_in[9];
    float* out = (float*)d_out;

    __nv_bfloat16 *xh, *xl, *whf, *wlf, *whr, *wlr;
    cudaGetSymbolAddress((void**)&xh,  g_xh);
    cudaGetSymbolAddress((void**)&xl,  g_xl);
    cudaGetSymbolAddress((void**)&whf, g_wh);
    cudaGetSymbolAddress((void**)&wlf, g_wl);
    whr = whf + (size_t)GG * DD;
    wlr = wlf + (size_t)GG * DD;

    split_bf16<<<(TT * BB * DD) / 1024, 256>>>(x, xh, xl);
    split_bf16<<<(GG * DD) / 1024, 256>>>(Wih_f, whf, wlf);
    split_bf16<<<(GG * DD) / 1024, 256>>>(Wih_r, whr, wlr);

    cudaFuncSetAttribute(precompute_mma,
                         cudaFuncAttributeMaxDynamicSharedMemorySize, PRE_SMEM);
    dim3 grid(GG / 128, (TT * BB) / 128, 2);
    precompute_mma<<<grid, 256, PRE_SMEM>>>(bih_f, bhh_f, bih_r, bhh_r);

    const int rec_smem = SMEM_FLOATS * 4;
    cudaFuncSetAttribute(lstm_rec_kernel,
                         cudaFuncAttributeMaxDynamicSharedMemorySize, rec_smem);
    lstm_rec_kernel<<<128, 128, rec_smem>>>(mask, Whh_f, Whh_r, out);
}

// round 13
// speedup vs baseline: 1.7438x; 1.4460x over previous
#include <cuda_runtime.h>
#include <cuda_bf16.h>
#include <math.h>
#include <stdint.h>

#define TT 512
#define BB 64
#define DD 512
#define HH 512
#define GG 2048   // 4H

// ---------------- scratch (static device allocations only) ----------------
__device__ float g_xg[2][TT * BB][GG];          // precomputed x@Wih^T + bias
__device__ __nv_bfloat16 g_hs[2][2][2][BB][HH]; // [buf][dir][hi/lo][b][k]
__device__ unsigned g_bar_count[2];
__device__ volatile unsigned g_bar_gen[2];
__device__ volatile unsigned g_flag[2][64];
__device__ __nv_bfloat16 g_xh[TT * BB * DD];    // x split hi
__device__ __nv_bfloat16 g_xl[TT * BB * DD];    // x split lo
__device__ __nv_bfloat16 g_wh[2][GG * DD];      // Wih split hi (per dir)
__device__ __nv_bfloat16 g_wl[2][GG * DD];      // Wih split lo

// ---------------- PTX helpers (baseline ISA only — no tcgen05!) ------------
__device__ __forceinline__ uint32_t smem_to_u32(const void* p) {
    uint32_t a;
    asm("{ .reg .u64 t; cvta.to.shared.u64 t, %1; cvt.u32.u64 %0, t; }"
        : "=r"(a) : "l"(p));
    return a;
}
__device__ __forceinline__ void cp_async16(uint32_t dst, const void* src) {
    asm volatile("cp.async.cg.shared.global [%0], [%1], 16;" :: "r"(dst), "l"(src));
}
__device__ __forceinline__ void cp_commit() { asm volatile("cp.async.commit_group;"); }
__device__ __forceinline__ void cp_wait0()  { asm volatile("cp.async.wait_group 0;"); }

__device__ __forceinline__ void ldsm_x4(uint32_t* r, uint32_t a) {
    asm volatile("ldmatrix.sync.aligned.m8n8.x4.shared.b16 {%0,%1,%2,%3}, [%4];"
                 : "=r"(r[0]), "=r"(r[1]), "=r"(r[2]), "=r"(r[3]) : "r"(a));
}
__device__ __forceinline__ void ldsm_x2(uint32_t* r, uint32_t a) {
    asm volatile("ldmatrix.sync.aligned.m8n8.x2.shared.b16 {%0,%1}, [%2];"
                 : "=r"(r[0]), "=r"(r[1]) : "r"(a));
}
__device__ __forceinline__ void mma16816(float* c, const uint32_t* a, const uint32_t* b) {
    asm volatile("mma.sync.aligned.m16n8k16.row.col.f32.bf16.bf16.f32 "
                 "{%0,%1,%2,%3}, {%4,%5,%6,%7}, {%8,%9}, {%0,%1,%2,%3};"
                 : "+f"(c[0]), "+f"(c[1]), "+f"(c[2]), "+f"(c[3])
                 : "r"(a[0]), "r"(a[1]), "r"(a[2]), "r"(a[3]), "r"(b[0]), "r"(b[1]));
}

// ---------------- grid barrier (rec init) -----------------------------------
__device__ __forceinline__ void dir_barrier(int dir, unsigned target) {
    __syncthreads();
    if (threadIdx.x == 0) {
        __threadfence();
        if (atomicAdd(&g_bar_count[dir], 1u) == 63u) {
            g_bar_count[dir] = 0u;
            __threadfence();
            g_bar_gen[dir] = target;
        } else {
            while ((int)(g_bar_gen[dir] - target) < 0) { }
            __threadfence();
        }
    }
    __syncthreads();
}

// ---------------- kernel 0: fp32 -> bf16 hi/lo split -------------------------
__global__ void __launch_bounds__(256)
split_bf16(const float* __restrict__ src, __nv_bfloat16* __restrict__ hi,
           __nv_bfloat16* __restrict__ lo) {
    int i = (blockIdx.x * 256 + threadIdx.x) * 4;
    float4 v = *(const float4*)(src + i);
    __nv_bfloat16 h[4], l[4];
    float f[4] = {v.x, v.y, v.z, v.w};
#pragma unroll
    for (int k = 0; k < 4; k++) {
        h[k] = __float2bfloat16(f[k]);
        l[k] = __float2bfloat16(f[k] - __bfloat162float(h[k]));
    }
    *(uint2*)(hi + i) = *(uint2*)h;
    *(uint2*)(lo + i) = *(uint2*)l;
}

// ---------------- kernel 1: mma.sync bf16-split precompute GEMM --------------
#define KC       32
#define ROW_B    80
#define TILE_PB  (128 * ROW_B)
#define STAGE_PB (4 * TILE_PB)
#define PRE_SMEM (512 + 2 * STAGE_PB)

__global__ void __launch_bounds__(256)
precompute_mma(const float* __restrict__ bih_f, const float* __restrict__ bhh_f,
               const float* __restrict__ bih_r, const float* __restrict__ bhh_r)
{
    extern __shared__ char smem[];
    float* bias_s = (float*)smem;
    const uint32_t tilesBase = smem_to_u32(smem) + 512;

    const int tid  = threadIdx.x;
    const int wid  = tid >> 5;
    const int lane = tid & 31;
    const int dir  = blockIdx.z;
    const int n0   = blockIdx.x * 128;
    const int m0   = blockIdx.y * 128;
    const int m_off = (wid >> 2) * 64;
    const int n_off = (wid & 3) * 32;

    const __nv_bfloat16* wh = g_wh[dir];
    const __nv_bfloat16* wl = g_wl[dir];
    const float* bi = dir ? bih_r : bih_f;
    const float* bh = dir ? bhh_r : bhh_f;
    if (tid < 128) bias_s[tid] = __ldg(bi + n0 + tid) + __ldg(bh + n0 + tid);

    auto load_chunk = [&](int c, int bf) {
        const uint32_t sbase = tilesBase + bf * STAGE_PB;
        const int k0 = c * KC;
#pragma unroll
        for (int j = 0; j < 8; j++) {
            int idx  = j * 256 + tid;
            int tile = idx >> 9;
            int u    = idx & 511;
            int row  = u >> 2, seg = u & 3;
            uint32_t dst = sbase + tile * TILE_PB + row * ROW_B + seg * 16;
            const __nv_bfloat16* src;
            if (tile < 2) {
                int m = m0 + row;
                int asrc = dir ? ((TT - 1 - (m >> 6)) * BB + (m & 63)) : m;
                src = (tile == 0 ? g_xh : g_xl) + (size_t)asrc * DD + k0 + seg * 8;
            } else {
                src = (tile == 2 ? wh : wl) + (size_t)(n0 + row) * DD + k0 + seg * 8;
            }
            cp_async16(dst, src);
        }
        cp_commit();
    };

    const uint32_t aOff = (uint32_t)((m_off + (lane & 15)) * ROW_B + (lane >> 4) * 16);
    const uint32_t bOff = (uint32_t)((n_off + (lane & 7)) * ROW_B + ((lane >> 3) & 1) * 16);

    float acc[4][4][4];
#pragma unroll
    for (int mt = 0; mt < 4; mt++)
#pragma unroll
        for (int nt = 0; nt < 4; nt++)
#pragma unroll
            for (int q = 0; q < 4; q++) acc[mt][nt][q] = 0.f;

    load_chunk(0, 0);

    for (int c = 0; c < 16; c++) {
        cp_wait0();
        __syncthreads();
        if (c < 15) load_chunk(c + 1, (c + 1) & 1);
        const uint32_t stage = tilesBase + (c & 1) * STAGE_PB;

#pragma unroll
        for (int kk = 0; kk < 2; kk++) {
            uint32_t bhf[4][2], blf[4][2];
#pragma unroll
            for (int nt = 0; nt < 4; nt++) {
                ldsm_x2(bhf[nt], stage + 2 * TILE_PB + bOff + nt * 8 * ROW_B + kk * 32);
                ldsm_x2(blf[nt], stage + 3 * TILE_PB + bOff + nt * 8 * ROW_B + kk * 32);
            }
#pragma unroll
            for (int mt = 0; mt < 4; mt++) {
                uint32_t ahf[4], alf[4];
                ldsm_x4(ahf, stage + 0 * TILE_PB + aOff + mt * 16 * ROW_B + kk * 32);
                ldsm_x4(alf, stage + 1 * TILE_PB + aOff + mt * 16 * ROW_B + kk * 32);
#pragma unroll
                for (int nt = 0; nt < 4; nt++) {
                    mma16816(acc[mt][nt], ahf, bhf[nt]);
                    mma16816(acc[mt][nt], ahf, blf[nt]);
                    mma16816(acc[mt][nt], alf, bhf[nt]);
                }
            }
        }
    }

    const int gid = lane >> 2, qid = lane & 3;
#pragma unroll
    for (int mt = 0; mt < 4; mt++) {
#pragma unroll
        for (int nt = 0; nt < 4; nt++) {
            int nl = n_off + nt * 8 + qid * 2;
            int ml0 = m_off + mt * 16 + gid;
            float2 v0 = make_float2(acc[mt][nt][0] + bias_s[nl],
                                    acc[mt][nt][1] + bias_s[nl + 1]);
            float2 v1 = make_float2(acc[mt][nt][2] + bias_s[nl],
                                    acc[mt][nt][3] + bias_s[nl + 1]);
            *(float2*)&g_xg[dir][m0 + ml0][n0 + nl]     = v0;
            *(float2*)&g_xg[dir][m0 + ml0 + 8][n0 + nl] = v1;
        }
    }
}

// ---------------- kernel 2: persistent recurrence, mma.sync ------------------
// 128 CTAs (64/dir), 128 thr = 4 warps. CTA: gates GEMM M=64(b) x N=32(j) x
// K=512 per step, bf16 hi/lo split, 3 MMA chains, fp32 acc. Whh slice split
// into smem once; h exchanged in global as bf16 hi/lo pairs.
#define W_PITCH  1040                 // 512*2 + 16 pad (conflict-free ldmatrix)
#define WH_OFF   0
#define WH_LO    (32 * W_PITCH)       // 33280
#define A_PITCH  272                  // 128*2 + 16 pad
#define AS_OFF   (2 * 32 * W_PITCH)   // 66560
#define AS_HL    (64 * A_PITCH)       // 17408
#define AS_STG   (2 * AS_HL)          // 34816
#define GS_OFF   (AS_OFF + 2 * AS_STG)   // 136192
#define REC_SMEM (GS_OFF + 64 * 36 * 4)  // 145408

__global__ void __launch_bounds__(128, 1)
lstm_rec_mma(const float* __restrict__ mask,
             const float* __restrict__ Whh_f,
             const float* __restrict__ Whh_r,
             float* __restrict__ out)
{
    extern __shared__ char smem[];
    const uint32_t sb = smem_to_u32(smem);
    float* Gs = (float*)(smem + GS_OFF);

    const int tid  = threadIdx.x;
    const int warp = tid >> 5;
    const int lane = tid & 31;
    const int cta  = blockIdx.x;
    const int dir  = cta >> 6;
    const int hc0  = (cta & 63) * 8;
    const int pu   = tid >> 4;        // pointwise h unit
    const int pb   = tid & 15;        // pointwise batch base
    const float* Whh = dir ? Whh_r : Whh_f;

    // ---- load + split Whh slice into smem (once) ----
    for (int q = tid; q < 32 * 512; q += 128) {
        int j = q >> 9, k = q & 511;
        int jg = (j >> 3) * 512 + hc0 + (j & 7);
        float w = __ldg(Whh + (size_t)jg * HH + k);
        __nv_bfloat16 hi = __float2bfloat16(w);
        __nv_bfloat16 lo = __float2bfloat16(w - __bfloat162float(hi));
        *(__nv_bfloat16*)(smem + WH_OFF + j * W_PITCH + k * 2) = hi;
        *(__nv_bfloat16*)(smem + WH_LO  + j * W_PITCH + k * 2) = lo;
    }

    // ---- zero own h slices (both buffers, hi+lo) ----
    for (int q = tid; q < 2048; q += 128) {
        int buf = q >> 10, hl = (q >> 9) & 1, b = (q >> 3) & 63, u = q & 7;
        g_hs[buf][dir][hl][b][hc0 + u] = __float2bfloat16(0.f);
    }
    if (tid == 0) g_flag[dir][cta & 63] = 0u;
    const unsigned gen0 = g_bar_gen[dir];
    dir_barrier(dir, gen0 + 1);

    // ldmatrix per-lane offsets
    const uint32_t aOff = (uint32_t)((warp * 16 + (lane & 15)) * A_PITCH + (lane >> 4) * 16);
    const uint32_t bOff = (uint32_t)(((lane & 7) + ((lane >> 4) & 1) * 8) * W_PITCH
                                     + ((lane >> 3) & 1) * 16);

    float c_reg[4]  = {0.f, 0.f, 0.f, 0.f};
    float h_prev[4] = {0.f, 0.f, 0.f, 0.f};

    for (int t = 0; t < TT; t++) {
        const int buf = t & 1;
        const int tt  = dir ? (TT - 1 - t) : t;
        const __nv_bfloat16* hsrc = &g_hs[buf][dir][0][0][0];

        // prefetch xg + mask (DRAM latency hidden under wait+GEMM)
        float xgi[4], xgf[4], xgg[4], xgo[4], mv[4];
#pragma unroll
        for (int i = 0; i < 4; i++) {
            const float* xr = &g_xg[dir][(size_t)t * BB + (i * 16 + pb)][0];
            xgi[i] = __ldg(xr + hc0 + pu);
            xgf[i] = __ldg(xr + 512 + hc0 + pu);
            xgg[i] = __ldg(xr + 1024 + hc0 + pu);
            xgo[i] = __ldg(xr + 1536 + hc0 + pu);
            mv[i]  = __ldg(&mask[tt * BB + i * 16 + pb]);
        }

        // wait for all h[t] slices
        if (tid < 64) {
            while (g_flag[dir][tid] < (unsigned)t) { }
        }
        __syncthreads();

        // A chunk loader: 64 rows x 128 k, hi+lo
        auto load_chunkA = [&](int kc, int stg) {
            const uint32_t base = sb + AS_OFF + stg * AS_STG;
#pragma unroll
            for (int j = 0; j < 16; j++) {
                int idx = j * 128 + tid;
                int hl  = idx >> 10;
                int u   = idx & 1023;
                int row = u >> 4, seg = u & 15;
                cp_async16(base + hl * AS_HL + row * A_PITCH + seg * 16,
                           hsrc + hl * (BB * HH) + row * HH + kc * 128 + seg * 8);
            }
            cp_commit();
        };

        load_chunkA(0, 0);

        float acc[4][4];   // [ntile][frag]
#pragma unroll
        for (int nt = 0; nt < 4; nt++)
#pragma unroll
            for (int q = 0; q < 4; q++) acc[nt][q] = 0.f;

        for (int kc = 0; kc < 4; kc++) {
            cp_wait0();
            __syncthreads();
            if (kc < 3) load_chunkA(kc + 1, (kc + 1) & 1);
            const uint32_t sA = sb + AS_OFF + (kc & 1) * AS_STG;

#pragma unroll
            for (int kk = 0; kk < 8; kk++) {
                uint32_t ah[4], al[4];
                ldsm_x4(ah, sA + aOff + kk * 32);
                ldsm_x4(al, sA + AS_HL + aOff + kk * 32);
                const uint32_t kb = (uint32_t)(kc * 256 + kk * 32);
                uint32_t bh01[4], bh23[4], bl01[4], bl23[4];
                ldsm_x4(bh01, sb + WH_OFF + bOff + kb);
                ldsm_x4(bh23, sb + WH_OFF + 16 * W_PITCH + bOff + kb);
                ldsm_x4(bl01, sb + WH_LO + bOff + kb);
                ldsm_x4(bl23, sb + WH_LO + 16 * W_PITCH + bOff + kb);

                mma16816(acc[0], ah, bh01);     mma16816(acc[1], ah, bh01 + 2);
                mma16816(acc[2], ah, bh23);     mma16816(acc[3], ah, bh23 + 2);
                mma16816(acc[0], ah, bl01);     mma16816(acc[1], ah, bl01 + 2);
                mma16816(acc[2], ah, bl23);     mma16816(acc[3], ah, bl23 + 2);
                mma16816(acc[0], al, bh01);     mma16816(acc[1], al, bh01 + 2);
                mma16816(acc[2], al, bh23);     mma16816(acc[3], al, bh23 + 2);
            }
        }

        // stage gate results: Gs[b][j]
        {
            const int gid = lane >> 2, qid = lane & 3;
            const int m0r = warp * 16 + gid;
#pragma unroll
            for (int nt = 0; nt < 4; nt++) {
                int j = nt * 8 + qid * 2;
                *(float2*)&Gs[m0r * 36 + j]       = make_float2(acc[nt][0], acc[nt][1]);
                *(float2*)&Gs[(m0r + 8) * 36 + j] = make_float2(acc[nt][2], acc[nt][3]);
            }
        }
        __syncthreads();

        // pointwise: thread owns (u=pu, b in {pb, pb+16, pb+32, pb+48})
#pragma unroll
        for (int i = 0; i < 4; i++) {
            int b = i * 16 + pb;
            float iv = xgi[i] + Gs[b * 36 + pu];
            float fv = xgf[i] + Gs[b * 36 + 8 + pu];
            float gv = xgg[i] + Gs[b * 36 + 16 + pu];
            float ov = xgo[i] + Gs[b * 36 + 24 + pu];
            iv = 1.f / (1.f + __expf(-iv));
            fv = 1.f / (1.f + __expf(-fv));
            gv = tanhf(gv);
            ov = 1.f / (1.f + __expf(-ov));

            float cn = fv * c_reg[i] + iv * gv;
            float hn = ov * tanhf(cn);
            float m  = mv[i];
            cn = m * cn + (1.f - m) * c_reg[i];
            hn = m * hn + (1.f - m) * h_prev[i];
            c_reg[i]  = cn;
            h_prev[i] = hn;

            __nv_bfloat16 hh = __float2bfloat16(hn);
            __nv_bfloat16 hl = __float2bfloat16(hn - __bfloat162float(hh));
            g_hs[buf ^ 1][dir][0][b][hc0 + pu] = hh;
            g_hs[buf ^ 1][dir][1][b][hc0 + pu] = hl;
            out[(size_t)tt * (BB * 2 * HH) + (size_t)b * (2 * HH)
                + (dir << 9) + hc0 + pu] = hn;
        }
        __syncthreads();
        if (tid == 0) {
            __threadfence();
            g_flag[dir][cta & 63] = (unsigned)(t + 1);
        }
    }
}

// ---------------- launch -----------------------------------------------------
extern "C" void kernel_launch(void* const* d_in, const int* in_sizes, int n_in,
                              void* d_out, int out_size) {
    const float* x     = (const float*)d_in[0];
    const float* mask  = (const float*)d_in[1];
    const float* Wih_f = (const float*)d_in[2];
    const float* Whh_f = (const float*)d_in[3];
    const float* bih_f = (const float*)d_in[4];
    const float* bhh_f = (const float*)d_in[5];
    const float* Wih_r = (const float*)d_in[6];
    const float* Whh_r = (const float*)d_in[7];
    const float* bih_r = (const float*)d_in[8];
    const float* bhh_r = (const float*)d_in[9];
    float* out = (float*)d_out;

    __nv_bfloat16 *xh, *xl, *whf, *wlf, *whr, *wlr;
    cudaGetSymbolAddress((void**)&xh,  g_xh);
    cudaGetSymbolAddress((void**)&xl,  g_xl);
    cudaGetSymbolAddress((void**)&whf, g_wh);
    cudaGetSymbolAddress((void**)&wlf, g_wl);
    whr = whf + (size_t)GG * DD;
    wlr = wlf + (size_t)GG * DD;

    split_bf16<<<(TT * BB * DD) / 1024, 256>>>(x, xh, xl);
    split_bf16<<<(GG * DD) / 1024, 256>>>(Wih_f, whf, wlf);
    split_bf16<<<(GG * DD) / 1024, 256>>>(Wih_r, whr, wlr);

    cudaFuncSetAttribute(precompute_mma,
                         cudaFuncAttributeMaxDynamicSharedMemorySize, PRE_SMEM);
    dim3 grid(GG / 128, (TT * BB) / 128, 2);
    precompute_mma<<<grid, 256, PRE_SMEM>>>(bih_f, bhh_f, bih_r, bhh_r);

    cudaFuncSetAttribute(lstm_rec_mma,
                         cudaFuncAttributeMaxDynamicSharedMemorySize, REC_SMEM);
    lstm_rec_mma<<<128, 128, REC_SMEM>>>(mask, Whh_f, Whh_r, out);
}